// round 17
// baseline (speedup 1.0000x reference)
#include <cuda_runtime.h>
#include <cuda_fp16.h>
#include <cuda_bf16.h>

// Problem constants (shapes are fixed by the dataset).
#define FH   200
#define FW   304
#define FC   256
#define FC3  768
#define H1   100
#define W1   152
#define H2   50
#define W2   76
#define OUTH 7
#define OUTW 7
#define NBINS 49   // 7*7
#define NSAMP 14   // 7*2 sample coords per axis
#define HTILE 4    // h rows per fuse block

// Fused feature map in HWC layout, fp16: g_fused[h][w][c], c fastest. ~93 MB.
__device__ __align__(16) __half g_fused[FH * FW * FC3];

// -------------------------------------------------------------------------
// Kernel 1: fuse (copy / bilinear-upsample) + transpose CHW -> HWC(fp16).
// Grid: x = 12 (64-ch tiles, fastest), y = 10 (w tiles of 32), z = 50 (h/4).
// Block: 32x8 = 256 threads.
// Upsample levels stage the coarse source tile (<=64ch x 4rows x 18cols)
// in smem ONCE per block with coalesced loads, then interpolate from smem —
// kills the 32-scalar-LDG-per-thread-per-row L1 bottleneck.
// -------------------------------------------------------------------------
__global__ void __launch_bounds__(256) fuse_kernel(
    const float* __restrict__ f0,
    const float* __restrict__ f1,
    const float* __restrict__ f2)
{
    __shared__ float tile[64][33];
    __shared__ float sc[64][73];          // coarse stage: pitch 73 (odd)

    const int tx = threadIdx.x;           // 0..31
    const int ty = threadIdx.y;           // 0..7
    const int t  = ty * 32 + tx;
    const int ct = blockIdx.x;            // 0..11 -> 64-channel tile
    const int w0 = blockIdx.y << 5;
    const int h0 = blockIdx.z * HTILE;
    const int lvl    = ct >> 2;           // 0,1,2
    const int clbase = (ct & 3) << 6;     // channel base within level
    const int w      = w0 + tx;
    const bool wok   = (w < FW);

    if (lvl == 0) {
        for (int hh = 0; hh < HTILE; hh++) {
            const int h = h0 + hh;
            #pragma unroll
            for (int r = 0; r < 8; r++) {
                const int c = clbase + (r << 3) + ty;
                tile[(r << 3) + ty][tx] = wok ? f0[(c * FH + h) * FW + w] : 0.0f;
            }
            __syncthreads();
            #pragma unroll
            for (int wl = ty; wl < 32; wl += 8) {
                const int wq = w0 + wl;
                if (wq < FW) {
                    __half2 hv = __floats2half2_rn(tile[2 * tx][wl], tile[2 * tx + 1][wl]);
                    *reinterpret_cast<__half2*>(
                        &g_fused[(h * FW + wq) * FC3 + (ct << 6) + (tx << 1)]) = hv;
                }
            }
            __syncthreads();
        }
        return;
    }

    // ---- upsample levels ----
    const float s   = (lvl == 1) ? 0.5f   : 0.25f;
    const float off = (lvl == 1) ? -0.25f : -0.375f;
    const int   SH  = (lvl == 1) ? H1 : H2;
    const int   SW  = (lvl == 1) ? W1 : W2;
    const float* __restrict__ src = (lvl == 1) ? f1 : f2;

    // block-level coarse region (monotone bounds)
    const int ry0 = max((int)floorf(s * (float)h0 + off), 0);
    const int ry1 = min((int)floorf(s * (float)(h0 + HTILE - 1) + off) + 1, SH - 1);
    const int rx0 = max((int)floorf(s * (float)w0 + off), 0);
    const int rx1 = min((int)floorf(s * (float)(w0 + 31) + off) + 1, SW - 1);
    const int nrows = ry1 - ry0 + 1;      // <= 4
    const int ncols = rx1 - rx0 + 1;      // <= 18
    const int span  = nrows * ncols;      // <= 72

    // cooperative coalesced stage of the coarse tile
    {
        const int total = 64 * span;
        for (int idx = t; idx < total; idx += 256) {
            const int c   = idx / span;
            const int rem = idx - c * span;
            const int rr  = rem / ncols;
            const int cc  = rem - rr * ncols;
            sc[c][rem] = src[(clbase + c) * (SH * SW) + (ry0 + rr) * SW + (rx0 + cc)];
        }
    }
    __syncthreads();

    // per-thread x-interp params (relative to staged tile)
    float xs = s * (float)w + off;
    float xf = floorf(xs);
    const float fx  = xs - xf;
    const int ix0r = max((int)xf, 0) - rx0;
    const int ix1r = min(max((int)xf, 0) + 1, SW - 1) - rx0;

    for (int hh = 0; hh < HTILE; hh++) {
        const int h = h0 + hh;
        float ys = s * (float)h + off;
        float yf = floorf(ys);
        const float fy = ys - yf;
        const int iy0r = max((int)yf, 0) - ry0;
        const int iy1r = min(max((int)yf, 0) + 1, SH - 1) - ry0;
        const float w00 = (1.0f - fy) * (1.0f - fx);
        const float w01 = (1.0f - fy) * fx;
        const float w10 = fy * (1.0f - fx);
        const float w11 = fy * fx;
        const int i00 = iy0r * ncols + ix0r, i01 = iy0r * ncols + ix1r;
        const int i10 = iy1r * ncols + ix0r, i11 = iy1r * ncols + ix1r;

        #pragma unroll
        for (int r = 0; r < 8; r++) {
            const int cl = (r << 3) + ty;
            const float* p = sc[cl];
            float v = w00 * p[i00] + w01 * p[i01] + w10 * p[i10] + w11 * p[i11];
            tile[cl][tx] = wok ? v : 0.0f;
        }
        __syncthreads();
        #pragma unroll
        for (int wl = ty; wl < 32; wl += 8) {
            const int wq = w0 + wl;
            if (wq < FW) {
                __half2 hv = __floats2half2_rn(tile[2 * tx][wl], tile[2 * tx + 1][wl]);
                *reinterpret_cast<__half2*>(
                    &g_fused[(h * FW + wq) * FC3 + (ct << 6) + (tx << 1)]) = hv;
            }
        }
        __syncthreads();
    }
}

// -------------------------------------------------------------------------
// Robust scalar decode: works for int32, little-endian int64, or float32.
// -------------------------------------------------------------------------
__device__ __forceinline__ float decode_dim(const void* p) {
    int iv = *(const int*)p;
    if (iv > 0 && iv < 1000000) return (float)iv;   // int32 / low word of int64
    float fv = __int_as_float(iv);
    if (fv > 0.0f && fv < 1000000.0f) return fv;    // float32
    return (float)iv;
}

// -------------------------------------------------------------------------
// Kernel 2: RoIAlign over the fused HWC fp16 map.
// Grid: (6 channel-chunks of 128, N boxes). Block: 256 threads.
//   t & 15  -> 8-channel group (16 groups * 8 = 128 channels), 16B gathers
//   t >> 4  -> bin slice (16 slices over 49 bins)
// Accumulates (fp32) into smem in output [c][bin] order, then block-copies
// contiguously to d_out (coalesced stores).
// -------------------------------------------------------------------------
__global__ void __launch_bounds__(256) roi_kernel(
    const float* __restrict__ boxes,
    const void*  __restrict__ pimh,
    const void*  __restrict__ pimw,
    float* __restrict__ out)
{
    const int chunk = blockIdx.x;   // 0..5
    const int n     = blockIdx.y;   // box
    const int cbase = chunk << 7;   // *128

    __shared__ __align__(16) float acc[128 * NBINS];   // 25088 B
    __shared__ int   sy0[NSAMP], sy1c[NSAMP], sx0[NSAMP], sx1c[NSAMP];
    __shared__ float shy[NSAMP], sly[NSAMP], shx[NSAMP], slx[NSAMP];

    const int t = threadIdx.x;

    if (t < 2 * NSAMP) {
        const bool isY = (t < NSAMP);
        const int  j   = isY ? t : t - NSAMP;
        const float dimImg  = isY ? decode_dim(pimh) : decode_dim(pimw);
        const float dimFeat = isY ? (float)FH : (float)FW;
        const float scale = dimFeat / dimImg;
        const float lo = boxes[n * 4 + (isY ? 1 : 0)] * scale;
        const float hi = boxes[n * 4 + (isY ? 3 : 2)] * scale;
        const float sz    = fmaxf(hi - lo, 1.0f);
        const float binsz = sz * (1.0f / 7.0f);
        const int   o = j >> 1, r = j & 1;
        const float coord = lo + ((float)o + 0.25f + 0.5f * (float)r) * binsz;
        const bool  valid = (coord >= -1.0f) && (coord <= dimFeat);
        const float cc = fminf(fmaxf(coord, 0.0f), dimFeat - 1.0f);
        const int   i0 = (int)floorf(cc);
        const int   i1 = min(i0 + 1, (int)dimFeat - 1);
        float l  = cc - (float)i0;
        float hw = 1.0f - l;
        if (!valid) { l = 0.0f; hw = 0.0f; }   // fold validity into weights
        if (isY) { sy0[j] = i0; sy1c[j] = i1; shy[j] = hw; sly[j] = l; }
        else     { sx0[j] = i0; sx1c[j] = i1; shx[j] = hw; slx[j] = l; }
    }
    __syncthreads();

    const int g     = t & 15;       // channel group of 8
    const int slice = t >> 4;       // 0..15
    const int cAbs  = cbase + (g << 3);
    const uint4* __restrict__ fp = reinterpret_cast<const uint4*>(g_fused);

    for (int bin = slice; bin < NBINS; bin += 16) {
        const int oh = bin / 7;
        const int ow = bin - oh * 7;
        float a0 = 0.f, a1 = 0.f, a2 = 0.f, a3 = 0.f;
        float a4 = 0.f, a5 = 0.f, a6 = 0.f, a7 = 0.f;

        #pragma unroll
        for (int ry = 0; ry < 2; ry++) {
            const int jy = (oh << 1) + ry;
            const int y0 = sy0[jy], y1 = sy1c[jy];
            const float hy = shy[jy], ly = sly[jy];
            const int rowA = (y0 * FW);
            const int rowB = (y1 * FW);
            #pragma unroll
            for (int rx = 0; rx < 2; rx++) {
                const int jx = (ow << 1) + rx;
                const int x0 = sx0[jx], x1 = sx1c[jx];
                const float hx = shx[jx], lx = slx[jx];
                const float w00 = hy * hx, w01 = hy * lx;
                const float w10 = ly * hx, w11 = ly * lx;
                const uint4 v00 = fp[(((rowA + x0) * FC3) + cAbs) >> 3];
                const uint4 v01 = fp[(((rowA + x1) * FC3) + cAbs) >> 3];
                const uint4 v10 = fp[(((rowB + x0) * FC3) + cAbs) >> 3];
                const uint4 v11 = fp[(((rowB + x1) * FC3) + cAbs) >> 3];
                #define ACC8(v, wgt) { \
                    const __half2* hp = reinterpret_cast<const __half2*>(&(v)); \
                    float2 p0 = __half22float2(hp[0]); \
                    float2 p1 = __half22float2(hp[1]); \
                    float2 p2 = __half22float2(hp[2]); \
                    float2 p3 = __half22float2(hp[3]); \
                    a0 += (wgt) * p0.x;  a1 += (wgt) * p0.y; \
                    a2 += (wgt) * p1.x;  a3 += (wgt) * p1.y; \
                    a4 += (wgt) * p2.x;  a5 += (wgt) * p2.y; \
                    a6 += (wgt) * p3.x;  a7 += (wgt) * p3.y; }
                ACC8(v00, w00); ACC8(v01, w01); ACC8(v10, w10); ACC8(v11, w11);
                #undef ACC8
            }
        }
        // mean over the 2x2 sampling grid (always /4)
        const int cL = g << 3;
        acc[(cL + 0) * NBINS + bin] = a0 * 0.25f;
        acc[(cL + 1) * NBINS + bin] = a1 * 0.25f;
        acc[(cL + 2) * NBINS + bin] = a2 * 0.25f;
        acc[(cL + 3) * NBINS + bin] = a3 * 0.25f;
        acc[(cL + 4) * NBINS + bin] = a4 * 0.25f;
        acc[(cL + 5) * NBINS + bin] = a5 * 0.25f;
        acc[(cL + 6) * NBINS + bin] = a6 * 0.25f;
        acc[(cL + 7) * NBINS + bin] = a7 * 0.25f;
    }
    __syncthreads();

    // Contiguous, coalesced copy of this (box, chunk) slab: 128*49 floats.
    const float4* s4 = reinterpret_cast<const float4*>(acc);
    float4* o4 = reinterpret_cast<float4*>(out + (size_t)n * (FC3 * NBINS) + cbase * NBINS);
    #pragma unroll 4
    for (int i = t; i < (128 * NBINS) / 4; i += 256) {
        o4[i] = s4[i];
    }
}

// -------------------------------------------------------------------------
// Launch. Inputs (metadata order): feat0, feat1, feat2, boxes, img_h, img_w.
// -------------------------------------------------------------------------
extern "C" void kernel_launch(void* const* d_in, const int* in_sizes, int n_in,
                              void* d_out, int out_size)
{
    const float* f0    = (const float*)d_in[0];
    const float* f1    = (const float*)d_in[1];
    const float* f2    = (const float*)d_in[2];
    const float* boxes = (const float*)d_in[3];
    const void*  pimh  = d_in[4];
    const void*  pimw  = d_in[5];
    const int N = in_sizes[3] / 4;

    dim3 b1(32, 8);
    dim3 g1(FC3 / 64, (FW + 31) / 32, FH / HTILE);
    fuse_kernel<<<g1, b1>>>(f0, f1, f2);

    dim3 g2(FC3 / 128, N);   // chunk fastest -> same-box blocks adjacent (L2 locality)
    roi_kernel<<<g2, 256>>>(boxes, pimh, pimw, (float*)d_out);
}